// round 14
// baseline (speedup 1.0000x reference)
#include <cuda_runtime.h>
#include <cuda_fp16.h>
#include <stdint.h>

// ---------------------------------------------------------------------------
// tcnn HashGrid encode: coords [N,3] in [0,1], table [16, 2^19, 2] f32.
// Output [N, 32] f32. Levels 0-4 dense, 5-15 spatial-hashed.
//
// R14: 12-warp blocks (384 thr) at occupancy 5 -> 60 resident warps/SM (94%,
// was 55/86%). Warps 0-10: hashed level w+5 (2 point groups). Warp 11: 320
// of the 640 dense pair-tasks (runs concurrently with the hashed phase).
// Remaining 320 dense tasks: lanes tid<320 (warps 0-9), one each. Per-warp
// work stays flat (~10-11 wf/lane) while L1 gets 9% more feeders.
// Hashed gather: fp16x2 (x4096) 16B-group LDG.128 covers both x-corners for
// 75% of points (PRIME_x==1, f = e ^ (gx^(gx+1))); predicated LDG else.
// Dense: 32B fp16 cell records, 2-lane pair-fetch (1 LDG.128 = 4 corners).
// ---------------------------------------------------------------------------

namespace {
constexpr int      NLV    = 16;
constexpr int      NDENSE = 5;
constexpr int      NHASH  = 11;
constexpr unsigned TSZ    = 1u << 19;
constexpr unsigned TMASK  = TSZ - 1u;
constexpr unsigned PRIME2 = 2654435761u;
constexpr unsigned PRIME3 = 805459861u;
constexpr int      PTS    = 64;            // points per block
constexpr int      THR    = 384;           // threads per block (12 warps)
constexpr float    FSCL   = 4096.0f;       // fp16 storage scale
constexpr float    FINV   = 1.0f / 4096.0f;

constexpr double spow(int l) {
    double v = 1.0;
    for (int i = 0; i < l; ++i) v *= 1.4472692012786865;
    return v;
}
constexpr double scaled(int l) { return 16.0 * spow(l) - 1.0; }
constexpr unsigned resd(int l) {
    double sc = scaled(l);
    unsigned f = (unsigned)sc;
    return f + (((double)f < sc) ? 1u : 0u) + 1u;
}
constexpr unsigned cells_below(int l) {
    unsigned o = 0;
    for (int i = 0; i < l; ++i) o += resd(i) * resd(i) * resd(i);
    return o;
}
constexpr unsigned TOTAL_CELLS = cells_below(NDENSE);
static_assert(resd(0) == 16 && resd(4) == 71, "dense res sanity");
static_assert((unsigned long long)resd(4)*resd(4)*resd(4) <= TSZ, "lvl4 dense");
static_assert((unsigned long long)resd(5)*resd(5)*resd(5) >  TSZ, "lvl5 hashed");
static_assert(TOTAL_CELLS == 532784u, "cell count");

constexpr unsigned REPACK_BLOCKS = (TOTAL_CELLS + 255u) / 256u;          // 2082
constexpr unsigned CONV_BLOCKS   = ((unsigned)NHASH << 19) / 8u / 256u;  // 2816
constexpr unsigned PREP_BLOCKS   = REPACK_BLOCKS + CONV_BLOCKS;
}

__constant__ float    c_scale[NLV] = {
    (float)scaled(0),(float)scaled(1),(float)scaled(2),(float)scaled(3),
    (float)scaled(4),(float)scaled(5),(float)scaled(6),(float)scaled(7),
    (float)scaled(8),(float)scaled(9),(float)scaled(10),(float)scaled(11),
    (float)scaled(12),(float)scaled(13),(float)scaled(14),(float)scaled(15)};
__constant__ unsigned c_res[NDENSE]  = {resd(0),resd(1),resd(2),resd(3),resd(4)};
__constant__ unsigned c_res2[NDENSE] = {resd(0)*resd(0),resd(1)*resd(1),
    resd(2)*resd(2),resd(3)*resd(3),resd(4)*resd(4)};
__constant__ unsigned c_coff[NDENSE] = {cells_below(0),cells_below(1),
    cells_below(2),cells_below(3),cells_below(4)};

// dense cell records: 2 x uint4 per cell. Half k (=dx): 4 fp16x2 words,
// word j = corner (dx=k, dy=j>>1, dz=j&1), values scaled by FSCL.
__device__ __align__(128) uint4    g_cells[(size_t)TOTAL_CELLS * 2];
__device__ __align__(128) unsigned g_half[(size_t)NHASH << 19];  // fp16x2 entries

__device__ __forceinline__ unsigned pack_h2(float a, float b) {
    const __half2 h = __floats2half2_rn(a * FSCL, b * FSCL);
    return *reinterpret_cast<const unsigned*>(&h);
}
__device__ __forceinline__ unsigned pack_u2(unsigned a, unsigned b) {
    return pack_h2(__uint_as_float(a), __uint_as_float(b));
}

// --- fused prep. Blocks [0, REPACK_BLOCKS): repack dense cells (latency-
// bound, scheduled first). Rest: convert hashed levels to scaled fp16x2,
// 8 entries/thread (4x LDG.128, MLP=4).
__global__ void hg_prep(const float2* __restrict__ table) {
    if (blockIdx.x >= REPACK_BLOCKS) {
        const unsigned gid = (blockIdx.x - REPACK_BLOCKS) * 256u + threadIdx.x;
        const uint4* __restrict__ srcv =
            reinterpret_cast<const uint4*>(table + ((size_t)NDENSE << 19));
        const uint4 a = __ldg(srcv + gid * 4u);
        const uint4 b = __ldg(srcv + gid * 4u + 1u);
        const uint4 c = __ldg(srcv + gid * 4u + 2u);
        const uint4 d = __ldg(srcv + gid * 4u + 3u);
        uint4 o0, o1;
        o0.x = pack_u2(a.x, a.y);  o0.y = pack_u2(a.z, a.w);
        o0.z = pack_u2(b.x, b.y);  o0.w = pack_u2(b.z, b.w);
        o1.x = pack_u2(c.x, c.y);  o1.y = pack_u2(c.z, c.w);
        o1.z = pack_u2(d.x, d.y);  o1.w = pack_u2(d.z, d.w);
        uint4* dst = reinterpret_cast<uint4*>(g_half + gid * 8u);
        dst[0] = o0;
        dst[1] = o1;
    } else {
        const unsigned cid = blockIdx.x * 256u + threadIdx.x;
        if (cid >= TOTAL_CELLS) return;

        int l = 0;
        #pragma unroll
        for (int i = 1; i < NDENSE; ++i) if (cid >= c_coff[i]) l = i;
        const unsigned res = c_res[l], res2 = c_res2[l];
        const unsigned local = cid - c_coff[l];
        const unsigned gz  = local / res2;
        const unsigned rem = local - gz * res2;
        const unsigned gy  = rem / res;
        const unsigned gx  = rem - gy * res;

        const unsigned R1  = res - 1u;
        const unsigned cx0 = gx,          cx1 = min(gx + 1u, R1);
        const unsigned cy0 = gy * res,    cy1 = min(gy + 1u, R1) * res;
        const unsigned cz0 = gz * res2,   cz1 = min(gz + 1u, R1) * res2;

        const float2* __restrict__ tbl = table + (size_t)l * (size_t)TSZ;
        uint4* dst = &g_cells[(size_t)cid * 2];
        {
            const float2 c00 = tbl[cx0+cy0+cz0], c01 = tbl[cx0+cy0+cz1];
            const float2 c10 = tbl[cx0+cy1+cz0], c11 = tbl[cx0+cy1+cz1];
            uint4 o;
            o.x = pack_h2(c00.x, c00.y);
            o.y = pack_h2(c01.x, c01.y);
            o.z = pack_h2(c10.x, c10.y);
            o.w = pack_h2(c11.x, c11.y);
            dst[0] = o;
        }
        {
            const float2 c00 = tbl[cx1+cy0+cz0], c01 = tbl[cx1+cy0+cz1];
            const float2 c10 = tbl[cx1+cy1+cz0], c11 = tbl[cx1+cy1+cz1];
            uint4 o;
            o.x = pack_h2(c00.x, c00.y);
            o.y = pack_h2(c01.x, c01.y);
            o.z = pack_h2(c10.x, c10.y);
            o.w = pack_h2(c11.x, c11.y);
            dst[1] = o;
        }
    }
}

// extract 32-bit word k (0..3) from a uint4
__device__ __forceinline__ unsigned ext4(const uint4& q, unsigned k) {
    return (k & 2u) ? ((k & 1u) ? q.w : q.z) : ((k & 1u) ? q.y : q.x);
}
__device__ __forceinline__ float2 h2f(unsigned u) {
    return __half22float2(*reinterpret_cast<const __half2*>(&u));
}

// one dense pair-task: d -> (lvl, pt, k=dx); lanes (2j,2j+1) hold k=0/1 of
// the same pt -> shfl_xor(1) completes the cell.
__device__ __forceinline__ void dense_task(
    int d, const float* __restrict__ s_c, float (*s_out)[33])
{
    const int lvl = d >> 7;
    const int pt  = (d >> 1) & 63;
    const int k   = d & 1;

    const float    sc   = c_scale[lvl];
    const unsigned res  = c_res[lvl];
    const unsigned res2 = c_res2[lvl];
    const unsigned coff = c_coff[lvl];

    const float x = s_c[pt*3+0], y = s_c[pt*3+1], z = s_c[pt*3+2];
    const float px = x*sc + 0.5f, py = y*sc + 0.5f, pz = z*sc + 0.5f;
    const float fx = floorf(px), fy = floorf(py), fz = floorf(pz);
    const float wx = px - fx,    wy = py - fy,    wz = pz - fz;
    const unsigned gx = (unsigned)fx, gy = (unsigned)fy, gz = (unsigned)fz;

    const unsigned cell = coff + gx + gy*res + gz*res2;
    const uint4 q = __ldg(&g_cells[(size_t)cell * 2 + k]);  // 4 corners

    const float iy = 1.0f - wy, iz = 1.0f - wz;
    const float w00 = iy*iz, w01 = iy*wz, w10 = wy*iz, w11 = wy*wz;
    const float2 c00 = h2f(q.x), c01 = h2f(q.y);
    const float2 c10 = h2f(q.z), c11 = h2f(q.w);
    const float wdx = k ? wx : 1.0f - wx;
    float f0 = wdx * (w00*c00.x + w01*c01.x + w10*c10.x + w11*c11.x);
    float f1 = wdx * (w00*c00.y + w01*c01.y + w10*c10.y + w11*c11.y);

    f0 += __shfl_xor_sync(0xffffffffu, f0, 1);
    f1 += __shfl_xor_sync(0xffffffffu, f1, 1);

    if (k == 0) {
        s_out[pt][2*lvl + 0] = f0 * FINV;
        s_out[pt][2*lvl + 1] = f1 * FINV;
    }
}

// --- main encode. Block = 384 threads = 12 warps, 64 points per block.
__global__ __launch_bounds__(THR, 5) void hg_encode(
    const float*  __restrict__ coords,
    float*        __restrict__ out,
    int n_points)
{
    __shared__ float s_c[PTS * 3];
    __shared__ float s_out[PTS][33];

    const int tid   = threadIdx.x;
    const int lane  = tid & 31;
    const int warp  = tid >> 5;
    const int pbase = blockIdx.x * PTS;

    if (tid < PTS * 3) {
        const int g = pbase * 3 + tid;
        s_c[tid] = (g < n_points * 3) ? coords[g] : 0.0f;
    }
    __syncthreads();

    if (warp < NHASH) {
        // ------------- hashed level (warps 0-10, 2 point groups) -----------
        const int level = warp + NDENSE;
        const float sc = c_scale[level];
        const unsigned* __restrict__ tb = g_half + ((size_t)warp << 19);
        const uint4*    __restrict__ tg = reinterpret_cast<const uint4*>(tb);

        #pragma unroll
        for (int grp = 0; grp < 2; ++grp) {
            const int pt = grp * 32 + lane;
            const float x = s_c[pt*3+0], y = s_c[pt*3+1], z = s_c[pt*3+2];

            const float px = x*sc + 0.5f, py = y*sc + 0.5f, pz = z*sc + 0.5f;
            const float fx = floorf(px), fy = floorf(py), fz = floorf(pz);
            const float wx = px - fx,    wy = py - fy,    wz = pz - fz;
            const unsigned gx = (unsigned)fx, gy = (unsigned)fy, gz = (unsigned)fz;

            const unsigned hy0 = gy * PRIME2, hy1 = hy0 + PRIME2;
            const unsigned hz0 = gz * PRIME3, hz1 = hz0 + PRIME3;
            const unsigned m   = gx ^ (gx + 1u);       // dx=1 corner: f = e ^ m
            const bool   extra = (m > 3u);             // f outside 16B group (25%)

            const float ix = 1.0f - wx, iy = 1.0f - wy, iz = 1.0f - wz;
            const float a00 = ix*iy, a01 = ix*wy, a10 = wx*iy, a11 = wx*wy;
            const float w0 = a00*iz, w1 = a00*wz, w2 = a01*iz, w3 = a01*wz;
            const float w4 = a10*iz, w5 = a10*wz, w6 = a11*iz, w7 = a11*wz;

            float r0, r1;
            // ---- batch A: corner-pairs j=0 (dy0,dz0), j=1 (dy0,dz1) ----
            {
                const unsigned e0 = (gx ^ hy0 ^ hz0) & TMASK;
                const unsigned e1 = (gx ^ hy0 ^ hz1) & TMASK;
                const uint4 q0 = __ldg(tg + (e0 >> 2));
                const uint4 q1 = __ldg(tg + (e1 >> 2));
                const unsigned f0 = e0 ^ m, f1 = e1 ^ m;
                const unsigned xb0 = extra ? __ldg(tb + f0) : 0u;   // @P LDG
                const unsigned xb1 = extra ? __ldg(tb + f1) : 0u;
                const unsigned a0 = ext4(q0, e0 & 3u);
                const unsigned a1 = ext4(q1, e1 & 3u);
                const unsigned b0 = extra ? xb0 : ext4(q0, f0 & 3u);
                const unsigned b1 = extra ? xb1 : ext4(q1, f1 & 3u);
                const float2 va0 = h2f(a0), va1 = h2f(a1);
                const float2 vb0 = h2f(b0), vb1 = h2f(b1);
                r0  = w0*va0.x + w1*va1.x + w4*vb0.x + w5*vb1.x;
                r1  = w0*va0.y + w1*va1.y + w4*vb0.y + w5*vb1.y;
            }
            // ---- batch B: corner-pairs j=2 (dy1,dz0), j=3 (dy1,dz1) ----
            {
                const unsigned e2 = (gx ^ hy1 ^ hz0) & TMASK;
                const unsigned e3 = (gx ^ hy1 ^ hz1) & TMASK;
                const uint4 q2 = __ldg(tg + (e2 >> 2));
                const uint4 q3 = __ldg(tg + (e3 >> 2));
                const unsigned f2 = e2 ^ m, f3 = e3 ^ m;
                const unsigned xb2 = extra ? __ldg(tb + f2) : 0u;
                const unsigned xb3 = extra ? __ldg(tb + f3) : 0u;
                const unsigned a2 = ext4(q2, e2 & 3u);
                const unsigned a3 = ext4(q3, e3 & 3u);
                const unsigned b2 = extra ? xb2 : ext4(q2, f2 & 3u);
                const unsigned b3 = extra ? xb3 : ext4(q3, f3 & 3u);
                const float2 va2 = h2f(a2), va3 = h2f(a3);
                const float2 vb2 = h2f(b2), vb3 = h2f(b3);
                r0 += w2*va2.x + w3*va3.x + w6*vb2.x + w7*vb3.x;
                r1 += w2*va2.y + w3*va3.y + w6*vb2.y + w7*vb3.y;
            }

            s_out[pt][2*level + 0] = r0 * FINV;
            s_out[pt][2*level + 1] = r1 * FINV;
        }
    } else {
        // ------------- dense warp (warp 11): tasks 0..319 ------------------
        #pragma unroll
        for (int i = 0; i < 10; ++i)
            dense_task(lane + 32 * i, s_c, s_out);
    }

    // remaining dense tasks 320..639: lanes tid<320 (warps 0-9), one each
    if (tid < 320)
        dense_task(320 + tid, s_c, s_out);
    __syncthreads();

    // Coalesced writeback: 1024 float2 = 8KB contiguous per block.
    #pragma unroll
    for (int idx = tid; idx < PTS * 16; idx += THR) {
        const int pp = idx >> 4;
        const int c  = (idx & 15) * 2;
        const int gp = pbase + pp;
        if (gp < n_points) {
            const float a = s_out[pp][c];
            const float b = s_out[pp][c + 1];
            float2* o = reinterpret_cast<float2*>(out + (size_t)gp * 32 + c);
            *o = make_float2(a, b);
        }
    }
}

extern "C" void kernel_launch(void* const* d_in, const int* in_sizes, int n_in,
                              void* d_out, int out_size) {
    const float*  coords = (const float*)d_in[0];   // [N, 3] f32
    const float2* table  = (const float2*)d_in[1];  // [16, 2^19, 2] f32
    float*        out    = (float*)d_out;           // [N, 32] f32
    const int n_points = in_sizes[0] / 3;

    hg_prep<<<PREP_BLOCKS, 256>>>(table);
    const int blocks = (n_points + PTS - 1) / PTS;
    hg_encode<<<blocks, THR>>>(coords, out, n_points);
}

// round 15
// speedup vs baseline: 1.0209x; 1.0209x over previous
#include <cuda_runtime.h>
#include <cuda_fp16.h>
#include <stdint.h>

// ---------------------------------------------------------------------------
// tcnn HashGrid encode: coords [N,3] in [0,1], table [16, 2^19, 2] f32.
// Output [N, 32] f32. Levels 0-4 dense, 5-15 spatial-hashed.
//
// Final (R12 config, best measured 230.8us; R14 showed occupancy >83% and
// 12-warp splits regress — L1 wavefront throughput is saturated at ~91% SOL
// and encode sits on its ~60 wavefront/point floor):
// - Block 352 thr = 11 warps, 64 pts, occupancy 5 (55 warps/SM).
// - Hashed (warps 0-10, level w+5, 2 unrolled point groups): table converted
//   per launch to scaled (x4096) fp16x2; aligned 16B-group LDG.128 covers
//   both x-corners for 75% of points (PRIME_x==1 -> f = e ^ (gx^(gx+1)) in
//   the same group when (gx&3)!=3); predicated LDG.32 for the rest.
//   -> 5 wavefronts/pt/lvl (vs 8 naive).
// - Dense: cells repacked to 32B fp16 records; 2-lane pair-fetch
//   (1 LDG.128 = 4 corners) + shfl_xor -> 1 wavefront/pt/lvl, spread flat
//   over all lanes.
// - Fused prep kernel (fp16 convert + dense repack, one launch, ~11us).
// - smem-staged coalesced output (8KB contiguous burst per block).
// ---------------------------------------------------------------------------

namespace {
constexpr int      NLV    = 16;
constexpr int      NDENSE = 5;
constexpr int      NHASH  = 11;
constexpr unsigned TSZ    = 1u << 19;
constexpr unsigned TMASK  = TSZ - 1u;
constexpr unsigned PRIME2 = 2654435761u;
constexpr unsigned PRIME3 = 805459861u;
constexpr int      PTS    = 64;            // points per block
constexpr float    FSCL   = 4096.0f;       // fp16 storage scale
constexpr float    FINV   = 1.0f / 4096.0f;

constexpr double spow(int l) {
    double v = 1.0;
    for (int i = 0; i < l; ++i) v *= 1.4472692012786865;
    return v;
}
constexpr double scaled(int l) { return 16.0 * spow(l) - 1.0; }
constexpr unsigned resd(int l) {
    double sc = scaled(l);
    unsigned f = (unsigned)sc;
    return f + (((double)f < sc) ? 1u : 0u) + 1u;
}
constexpr unsigned cells_below(int l) {
    unsigned o = 0;
    for (int i = 0; i < l; ++i) o += resd(i) * resd(i) * resd(i);
    return o;
}
constexpr unsigned TOTAL_CELLS = cells_below(NDENSE);
static_assert(resd(0) == 16 && resd(4) == 71, "dense res sanity");
static_assert((unsigned long long)resd(4)*resd(4)*resd(4) <= TSZ, "lvl4 dense");
static_assert((unsigned long long)resd(5)*resd(5)*resd(5) >  TSZ, "lvl5 hashed");
static_assert(TOTAL_CELLS == 532784u, "cell count");

constexpr unsigned HALF_BLOCKS   = ((unsigned)NHASH << 19) / 4u / 256u;  // 5632
constexpr unsigned REPACK_BLOCKS = (TOTAL_CELLS + 255u) / 256u;          // 2082
constexpr unsigned PREP_BLOCKS   = HALF_BLOCKS + REPACK_BLOCKS;
}

__constant__ float    c_scale[NLV] = {
    (float)scaled(0),(float)scaled(1),(float)scaled(2),(float)scaled(3),
    (float)scaled(4),(float)scaled(5),(float)scaled(6),(float)scaled(7),
    (float)scaled(8),(float)scaled(9),(float)scaled(10),(float)scaled(11),
    (float)scaled(12),(float)scaled(13),(float)scaled(14),(float)scaled(15)};
__constant__ unsigned c_res[NDENSE]  = {resd(0),resd(1),resd(2),resd(3),resd(4)};
__constant__ unsigned c_res2[NDENSE] = {resd(0)*resd(0),resd(1)*resd(1),
    resd(2)*resd(2),resd(3)*resd(3),resd(4)*resd(4)};
__constant__ unsigned c_coff[NDENSE] = {cells_below(0),cells_below(1),
    cells_below(2),cells_below(3),cells_below(4)};

// dense cell records: 2 x uint4 per cell. Half k (=dx): 4 fp16x2 words,
// word j = corner (dx=k, dy=j>>1, dz=j&1), values scaled by FSCL.
__device__ __align__(128) uint4    g_cells[(size_t)TOTAL_CELLS * 2];
__device__ __align__(128) unsigned g_half[(size_t)NHASH << 19];  // fp16x2 entries

__device__ __forceinline__ unsigned pack_h2(float a, float b) {
    const __half2 h = __floats2half2_rn(a * FSCL, b * FSCL);
    return *reinterpret_cast<const unsigned*>(&h);
}
__device__ __forceinline__ unsigned pack_u2(unsigned a, unsigned b) {
    return pack_h2(__uint_as_float(a), __uint_as_float(b));
}

// --- fused prep: blocks [0, HALF_BLOCKS) convert hashed levels to scaled
// fp16x2 (4 entries/thread, uint4-vectorized); rest repack dense cells.
__global__ void hg_prep(const float2* __restrict__ table) {
    if (blockIdx.x < HALF_BLOCKS) {
        const unsigned gid = blockIdx.x * 256u + threadIdx.x;
        const uint4* __restrict__ srcv =
            reinterpret_cast<const uint4*>(table + ((size_t)NDENSE << 19));
        const uint4 a = __ldg(srcv + gid * 2u);        // entries 4g, 4g+1
        const uint4 b = __ldg(srcv + gid * 2u + 1u);   // entries 4g+2, 4g+3
        uint4 o;
        o.x = pack_u2(a.x, a.y);
        o.y = pack_u2(a.z, a.w);
        o.z = pack_u2(b.x, b.y);
        o.w = pack_u2(b.z, b.w);
        *reinterpret_cast<uint4*>(g_half + gid * 4u) = o;
    } else {
        const unsigned cid = (blockIdx.x - HALF_BLOCKS) * 256u + threadIdx.x;
        if (cid >= TOTAL_CELLS) return;

        int l = 0;
        #pragma unroll
        for (int i = 1; i < NDENSE; ++i) if (cid >= c_coff[i]) l = i;
        const unsigned res = c_res[l], res2 = c_res2[l];
        const unsigned local = cid - c_coff[l];
        const unsigned gz  = local / res2;
        const unsigned rem = local - gz * res2;
        const unsigned gy  = rem / res;
        const unsigned gx  = rem - gy * res;

        const unsigned R1  = res - 1u;
        const unsigned cx0 = gx,          cx1 = min(gx + 1u, R1);
        const unsigned cy0 = gy * res,    cy1 = min(gy + 1u, R1) * res;
        const unsigned cz0 = gz * res2,   cz1 = min(gz + 1u, R1) * res2;

        const float2* __restrict__ tbl = table + (size_t)l * (size_t)TSZ;
        uint4* dst = &g_cells[(size_t)cid * 2];
        // half k=0 (dx=0): words j = dy*2+dz
        {
            const float2 c00 = tbl[cx0+cy0+cz0], c01 = tbl[cx0+cy0+cz1];
            const float2 c10 = tbl[cx0+cy1+cz0], c11 = tbl[cx0+cy1+cz1];
            uint4 o;
            o.x = pack_h2(c00.x, c00.y);
            o.y = pack_h2(c01.x, c01.y);
            o.z = pack_h2(c10.x, c10.y);
            o.w = pack_h2(c11.x, c11.y);
            dst[0] = o;
        }
        // half k=1 (dx=1)
        {
            const float2 c00 = tbl[cx1+cy0+cz0], c01 = tbl[cx1+cy0+cz1];
            const float2 c10 = tbl[cx1+cy1+cz0], c11 = tbl[cx1+cy1+cz1];
            uint4 o;
            o.x = pack_h2(c00.x, c00.y);
            o.y = pack_h2(c01.x, c01.y);
            o.z = pack_h2(c10.x, c10.y);
            o.w = pack_h2(c11.x, c11.y);
            dst[1] = o;
        }
    }
}

// extract 32-bit word k (0..3) from a uint4
__device__ __forceinline__ unsigned ext4(const uint4& q, unsigned k) {
    return (k & 2u) ? ((k & 1u) ? q.w : q.z) : ((k & 1u) ? q.y : q.x);
}
__device__ __forceinline__ float2 h2f(unsigned u) {
    return __half22float2(*reinterpret_cast<const __half2*>(&u));
}

// --- main encode. Block = 352 threads = 11 warps, 64 points per block.
__global__ __launch_bounds__(352, 5) void hg_encode(
    const float*  __restrict__ coords,
    float*        __restrict__ out,
    int n_points)
{
    __shared__ float s_c[PTS * 3];
    __shared__ float s_out[PTS][33];

    const int tid   = threadIdx.x;
    const int lane  = tid & 31;
    const int warp  = tid >> 5;
    const int pbase = blockIdx.x * PTS;

    if (tid < PTS * 3) {
        const int g = pbase * 3 + tid;
        s_c[tid] = (g < n_points * 3) ? coords[g] : 0.0f;
    }
    __syncthreads();

    // ---------------- hashed level (all 11 warps, 2 point groups) ----------
    {
        const int level = warp + NDENSE;
        const float sc = c_scale[level];
        const unsigned* __restrict__ tb = g_half + ((size_t)warp << 19);
        const uint4*    __restrict__ tg = reinterpret_cast<const uint4*>(tb);

        #pragma unroll
        for (int grp = 0; grp < 2; ++grp) {
            const int pt = grp * 32 + lane;
            const float x = s_c[pt*3+0], y = s_c[pt*3+1], z = s_c[pt*3+2];

            const float px = x*sc + 0.5f, py = y*sc + 0.5f, pz = z*sc + 0.5f;
            const float fx = floorf(px), fy = floorf(py), fz = floorf(pz);
            const float wx = px - fx,    wy = py - fy,    wz = pz - fz;
            const unsigned gx = (unsigned)fx, gy = (unsigned)fy, gz = (unsigned)fz;

            const unsigned hy0 = gy * PRIME2, hy1 = hy0 + PRIME2;
            const unsigned hz0 = gz * PRIME3, hz1 = hz0 + PRIME3;
            const unsigned m   = gx ^ (gx + 1u);       // dx=1 corner: f = e ^ m
            const bool   extra = (m > 3u);             // f outside 16B group (25%)

            const float ix = 1.0f - wx, iy = 1.0f - wy, iz = 1.0f - wz;
            const float a00 = ix*iy, a01 = ix*wy, a10 = wx*iy, a11 = wx*wy;
            const float w0 = a00*iz, w1 = a00*wz, w2 = a01*iz, w3 = a01*wz;
            const float w4 = a10*iz, w5 = a10*wz, w6 = a11*iz, w7 = a11*wz;

            float r0, r1;
            // ---- batch A: corner-pairs j=0 (dy0,dz0), j=1 (dy0,dz1) ----
            {
                const unsigned e0 = (gx ^ hy0 ^ hz0) & TMASK;
                const unsigned e1 = (gx ^ hy0 ^ hz1) & TMASK;
                const uint4 q0 = __ldg(tg + (e0 >> 2));
                const uint4 q1 = __ldg(tg + (e1 >> 2));
                const unsigned f0 = e0 ^ m, f1 = e1 ^ m;
                const unsigned xb0 = extra ? __ldg(tb + f0) : 0u;   // @P LDG
                const unsigned xb1 = extra ? __ldg(tb + f1) : 0u;
                const unsigned a0 = ext4(q0, e0 & 3u);
                const unsigned a1 = ext4(q1, e1 & 3u);
                const unsigned b0 = extra ? xb0 : ext4(q0, f0 & 3u);
                const unsigned b1 = extra ? xb1 : ext4(q1, f1 & 3u);
                const float2 va0 = h2f(a0), va1 = h2f(a1);
                const float2 vb0 = h2f(b0), vb1 = h2f(b1);
                r0  = w0*va0.x + w1*va1.x + w4*vb0.x + w5*vb1.x;
                r1  = w0*va0.y + w1*va1.y + w4*vb0.y + w5*vb1.y;
            }
            // ---- batch B: corner-pairs j=2 (dy1,dz0), j=3 (dy1,dz1) ----
            {
                const unsigned e2 = (gx ^ hy1 ^ hz0) & TMASK;
                const unsigned e3 = (gx ^ hy1 ^ hz1) & TMASK;
                const uint4 q2 = __ldg(tg + (e2 >> 2));
                const uint4 q3 = __ldg(tg + (e3 >> 2));
                const unsigned f2 = e2 ^ m, f3 = e3 ^ m;
                const unsigned xb2 = extra ? __ldg(tb + f2) : 0u;
                const unsigned xb3 = extra ? __ldg(tb + f3) : 0u;
                const unsigned a2 = ext4(q2, e2 & 3u);
                const unsigned a3 = ext4(q3, e3 & 3u);
                const unsigned b2 = extra ? xb2 : ext4(q2, f2 & 3u);
                const unsigned b3 = extra ? xb3 : ext4(q3, f3 & 3u);
                const float2 va2 = h2f(a2), va3 = h2f(a3);
                const float2 vb2 = h2f(b2), vb3 = h2f(b3);
                r0 += w2*va2.x + w3*va3.x + w6*vb2.x + w7*vb3.x;
                r1 += w2*va2.y + w3*va3.y + w6*vb2.y + w7*vb3.y;
            }

            s_out[pt][2*level + 0] = r0 * FINV;
            s_out[pt][2*level + 1] = r1 * FINV;
        }
    }

    // ---------------- dense levels: 640 pair-tasks over all lanes ----------
    // task d: lvl = d>>7 (128 tasks/level), pt = (d>>1)&63, k = d&1 (=dx).
    // Pairs (2 consecutive d) stay within one warp: 352 % 2 == 0.
    #pragma unroll
    for (int pass = 0; pass < 2; ++pass) {
        const int d = tid + pass * 352;
        if (d < 640) {
            const int lvl = d >> 7;
            const int pt  = (d >> 1) & 63;
            const int k   = d & 1;           // dx

            const float    sc   = c_scale[lvl];
            const unsigned res  = c_res[lvl];
            const unsigned res2 = c_res2[lvl];
            const unsigned coff = c_coff[lvl];

            const float x = s_c[pt*3+0], y = s_c[pt*3+1], z = s_c[pt*3+2];
            const float px = x*sc + 0.5f, py = y*sc + 0.5f, pz = z*sc + 0.5f;
            const float fx = floorf(px), fy = floorf(py), fz = floorf(pz);
            const float wx = px - fx,    wy = py - fy,    wz = pz - fz;
            const unsigned gx = (unsigned)fx, gy = (unsigned)fy, gz = (unsigned)fz;

            const unsigned cell = coff + gx + gy*res + gz*res2;
            const uint4 q = __ldg(&g_cells[(size_t)cell * 2 + k]);  // 4 corners

            const float iy = 1.0f - wy, iz = 1.0f - wz;
            const float w00 = iy*iz, w01 = iy*wz, w10 = wy*iz, w11 = wy*wz;
            const float2 c00 = h2f(q.x), c01 = h2f(q.y);
            const float2 c10 = h2f(q.z), c11 = h2f(q.w);
            const float wdx = k ? wx : 1.0f - wx;
            float f0 = wdx * (w00*c00.x + w01*c01.x + w10*c10.x + w11*c11.x);
            float f1 = wdx * (w00*c00.y + w01*c01.y + w10*c10.y + w11*c11.y);

            f0 += __shfl_xor_sync(0xffffffffu, f0, 1);
            f1 += __shfl_xor_sync(0xffffffffu, f1, 1);

            if (k == 0) {
                s_out[pt][2*lvl + 0] = f0 * FINV;
                s_out[pt][2*lvl + 1] = f1 * FINV;
            }
        }
    }
    __syncthreads();

    // Coalesced writeback: 1024 float2 = 8KB contiguous per block.
    #pragma unroll
    for (int idx = tid; idx < PTS * 16; idx += 352) {
        const int pp = idx >> 4;
        const int c  = (idx & 15) * 2;
        const int gp = pbase + pp;
        if (gp < n_points) {
            const float a = s_out[pp][c];
            const float b = s_out[pp][c + 1];
            float2* o = reinterpret_cast<float2*>(out + (size_t)gp * 32 + c);
            *o = make_float2(a, b);
        }
    }
}

extern "C" void kernel_launch(void* const* d_in, const int* in_sizes, int n_in,
                              void* d_out, int out_size) {
    const float*  coords = (const float*)d_in[0];   // [N, 3] f32
    const float2* table  = (const float2*)d_in[1];  // [16, 2^19, 2] f32
    float*        out    = (float*)d_out;           // [N, 32] f32
    const int n_points = in_sizes[0] / 3;

    hg_prep<<<PREP_BLOCKS, 256>>>(table);
    const int blocks = (n_points + PTS - 1) / PTS;
    hg_encode<<<blocks, 352>>>(coords, out, n_points);
}

// round 16
// speedup vs baseline: 1.0261x; 1.0051x over previous
#include <cuda_runtime.h>
#include <cuda_fp16.h>
#include <stdint.h>

// ---------------------------------------------------------------------------
// tcnn HashGrid encode: coords [N,3] in [0,1], table [16, 2^19, 2] f32.
// Output [N, 32] f32. Levels 0-4 dense, 5-15 spatial-hashed.
//
// Converged design (R12 skeleton, measured best 230.8us; encode at ~91% L1
// SOL on its ~60 wavefront/point floor; occ>83% and 12-warp splits measured
// worse; Morton sort and sub-fp16 quantization fail the cost/error math):
// - Block 352 thr = 11 warps, 64 pts, occupancy 5 (55 warps/SM).
// - Hashed (warps 0-10, level w+5, 2 unrolled point groups): table converted
//   per launch to scaled (x4096) fp16x2; aligned 16B-group LDG.128 covers
//   both x-corners for 75% of points (PRIME_x==1 -> f = e ^ (gx^(gx+1)) in
//   the same group when (gx&3)!=3); predicated LDG.32 for the rest.
//   -> 5 wavefronts/pt/lvl (vs 8 naive).
// - Dense: cells repacked to 32B fp16 records; 2-lane pair-fetch
//   (1 LDG.128 = 4 corners) + shfl_xor -> 1 wavefront/pt/lvl.
// - R16 micro: FINV de-scale folded into the z-weights (6 fewer FMULs/pt).
// - Fused prep kernel (fp16 convert + dense repack, one launch).
// - smem-staged coalesced output (8KB contiguous burst per block).
// ---------------------------------------------------------------------------

namespace {
constexpr int      NLV    = 16;
constexpr int      NDENSE = 5;
constexpr int      NHASH  = 11;
constexpr unsigned TSZ    = 1u << 19;
constexpr unsigned TMASK  = TSZ - 1u;
constexpr unsigned PRIME2 = 2654435761u;
constexpr unsigned PRIME3 = 805459861u;
constexpr int      PTS    = 64;            // points per block
constexpr float    FSCL   = 4096.0f;       // fp16 storage scale
constexpr float    FINV   = 1.0f / 4096.0f;

constexpr double spow(int l) {
    double v = 1.0;
    for (int i = 0; i < l; ++i) v *= 1.4472692012786865;
    return v;
}
constexpr double scaled(int l) { return 16.0 * spow(l) - 1.0; }
constexpr unsigned resd(int l) {
    double sc = scaled(l);
    unsigned f = (unsigned)sc;
    return f + (((double)f < sc) ? 1u : 0u) + 1u;
}
constexpr unsigned cells_below(int l) {
    unsigned o = 0;
    for (int i = 0; i < l; ++i) o += resd(i) * resd(i) * resd(i);
    return o;
}
constexpr unsigned TOTAL_CELLS = cells_below(NDENSE);
static_assert(resd(0) == 16 && resd(4) == 71, "dense res sanity");
static_assert((unsigned long long)resd(4)*resd(4)*resd(4) <= TSZ, "lvl4 dense");
static_assert((unsigned long long)resd(5)*resd(5)*resd(5) >  TSZ, "lvl5 hashed");
static_assert(TOTAL_CELLS == 532784u, "cell count");

constexpr unsigned HALF_BLOCKS   = ((unsigned)NHASH << 19) / 4u / 256u;  // 5632
constexpr unsigned REPACK_BLOCKS = (TOTAL_CELLS + 255u) / 256u;          // 2082
constexpr unsigned PREP_BLOCKS   = HALF_BLOCKS + REPACK_BLOCKS;
}

__constant__ float    c_scale[NLV] = {
    (float)scaled(0),(float)scaled(1),(float)scaled(2),(float)scaled(3),
    (float)scaled(4),(float)scaled(5),(float)scaled(6),(float)scaled(7),
    (float)scaled(8),(float)scaled(9),(float)scaled(10),(float)scaled(11),
    (float)scaled(12),(float)scaled(13),(float)scaled(14),(float)scaled(15)};
__constant__ unsigned c_res[NDENSE]  = {resd(0),resd(1),resd(2),resd(3),resd(4)};
__constant__ unsigned c_res2[NDENSE] = {resd(0)*resd(0),resd(1)*resd(1),
    resd(2)*resd(2),resd(3)*resd(3),resd(4)*resd(4)};
__constant__ unsigned c_coff[NDENSE] = {cells_below(0),cells_below(1),
    cells_below(2),cells_below(3),cells_below(4)};

// dense cell records: 2 x uint4 per cell. Half k (=dx): 4 fp16x2 words,
// word j = corner (dx=k, dy=j>>1, dz=j&1), values scaled by FSCL.
__device__ __align__(128) uint4    g_cells[(size_t)TOTAL_CELLS * 2];
__device__ __align__(128) unsigned g_half[(size_t)NHASH << 19];  // fp16x2 entries

__device__ __forceinline__ unsigned pack_h2(float a, float b) {
    const __half2 h = __floats2half2_rn(a * FSCL, b * FSCL);
    return *reinterpret_cast<const unsigned*>(&h);
}
__device__ __forceinline__ unsigned pack_u2(unsigned a, unsigned b) {
    return pack_h2(__uint_as_float(a), __uint_as_float(b));
}

// --- fused prep: blocks [0, HALF_BLOCKS) convert hashed levels to scaled
// fp16x2 (4 entries/thread, uint4-vectorized); rest repack dense cells.
__global__ void hg_prep(const float2* __restrict__ table) {
    if (blockIdx.x < HALF_BLOCKS) {
        const unsigned gid = blockIdx.x * 256u + threadIdx.x;
        const uint4* __restrict__ srcv =
            reinterpret_cast<const uint4*>(table + ((size_t)NDENSE << 19));
        const uint4 a = __ldg(srcv + gid * 2u);        // entries 4g, 4g+1
        const uint4 b = __ldg(srcv + gid * 2u + 1u);   // entries 4g+2, 4g+3
        uint4 o;
        o.x = pack_u2(a.x, a.y);
        o.y = pack_u2(a.z, a.w);
        o.z = pack_u2(b.x, b.y);
        o.w = pack_u2(b.z, b.w);
        *reinterpret_cast<uint4*>(g_half + gid * 4u) = o;
    } else {
        const unsigned cid = (blockIdx.x - HALF_BLOCKS) * 256u + threadIdx.x;
        if (cid >= TOTAL_CELLS) return;

        int l = 0;
        #pragma unroll
        for (int i = 1; i < NDENSE; ++i) if (cid >= c_coff[i]) l = i;
        const unsigned res = c_res[l], res2 = c_res2[l];
        const unsigned local = cid - c_coff[l];
        const unsigned gz  = local / res2;
        const unsigned rem = local - gz * res2;
        const unsigned gy  = rem / res;
        const unsigned gx  = rem - gy * res;

        const unsigned R1  = res - 1u;
        const unsigned cx0 = gx,          cx1 = min(gx + 1u, R1);
        const unsigned cy0 = gy * res,    cy1 = min(gy + 1u, R1) * res;
        const unsigned cz0 = gz * res2,   cz1 = min(gz + 1u, R1) * res2;

        const float2* __restrict__ tbl = table + (size_t)l * (size_t)TSZ;
        uint4* dst = &g_cells[(size_t)cid * 2];
        // half k=0 (dx=0): words j = dy*2+dz
        {
            const float2 c00 = tbl[cx0+cy0+cz0], c01 = tbl[cx0+cy0+cz1];
            const float2 c10 = tbl[cx0+cy1+cz0], c11 = tbl[cx0+cy1+cz1];
            uint4 o;
            o.x = pack_h2(c00.x, c00.y);
            o.y = pack_h2(c01.x, c01.y);
            o.z = pack_h2(c10.x, c10.y);
            o.w = pack_h2(c11.x, c11.y);
            dst[0] = o;
        }
        // half k=1 (dx=1)
        {
            const float2 c00 = tbl[cx1+cy0+cz0], c01 = tbl[cx1+cy0+cz1];
            const float2 c10 = tbl[cx1+cy1+cz0], c11 = tbl[cx1+cy1+cz1];
            uint4 o;
            o.x = pack_h2(c00.x, c00.y);
            o.y = pack_h2(c01.x, c01.y);
            o.z = pack_h2(c10.x, c10.y);
            o.w = pack_h2(c11.x, c11.y);
            dst[1] = o;
        }
    }
}

// extract 32-bit word k (0..3) from a uint4
__device__ __forceinline__ unsigned ext4(const uint4& q, unsigned k) {
    return (k & 2u) ? ((k & 1u) ? q.w : q.z) : ((k & 1u) ? q.y : q.x);
}
__device__ __forceinline__ float2 h2f(unsigned u) {
    return __half22float2(*reinterpret_cast<const __half2*>(&u));
}

// --- main encode. Block = 352 threads = 11 warps, 64 points per block.
__global__ __launch_bounds__(352, 5) void hg_encode(
    const float*  __restrict__ coords,
    float*        __restrict__ out,
    int n_points)
{
    __shared__ float s_c[PTS * 3];
    __shared__ float s_out[PTS][33];

    const int tid   = threadIdx.x;
    const int lane  = tid & 31;
    const int warp  = tid >> 5;
    const int pbase = blockIdx.x * PTS;

    if (tid < PTS * 3) {
        const int g = pbase * 3 + tid;
        s_c[tid] = (g < n_points * 3) ? coords[g] : 0.0f;
    }
    __syncthreads();

    // ---------------- hashed level (all 11 warps, 2 point groups) ----------
    {
        const int level = warp + NDENSE;
        const float sc = c_scale[level];
        const unsigned* __restrict__ tb = g_half + ((size_t)warp << 19);
        const uint4*    __restrict__ tg = reinterpret_cast<const uint4*>(tb);

        #pragma unroll
        for (int grp = 0; grp < 2; ++grp) {
            const int pt = grp * 32 + lane;
            const float x = s_c[pt*3+0], y = s_c[pt*3+1], z = s_c[pt*3+2];

            const float px = x*sc + 0.5f, py = y*sc + 0.5f, pz = z*sc + 0.5f;
            const float fx = floorf(px), fy = floorf(py), fz = floorf(pz);
            const float wx = px - fx,    wy = py - fy,    wz = pz - fz;
            const unsigned gx = (unsigned)fx, gy = (unsigned)fy, gz = (unsigned)fz;

            const unsigned hy0 = gy * PRIME2, hy1 = hy0 + PRIME2;
            const unsigned hz0 = gz * PRIME3, hz1 = hz0 + PRIME3;
            const unsigned m   = gx ^ (gx + 1u);       // dx=1 corner: f = e ^ m
            const bool   extra = (m > 3u);             // f outside 16B group (25%)

            // FINV de-scale folded into the z-weights (saves 2 trailing FMULs)
            const float ix = 1.0f - wx, iy = 1.0f - wy;
            const float izf = (1.0f - wz) * FINV, wzf = wz * FINV;
            const float a00 = ix*iy, a01 = ix*wy, a10 = wx*iy, a11 = wx*wy;
            const float w0 = a00*izf, w1 = a00*wzf, w2 = a01*izf, w3 = a01*wzf;
            const float w4 = a10*izf, w5 = a10*wzf, w6 = a11*izf, w7 = a11*wzf;

            float r0, r1;
            // ---- batch A: corner-pairs j=0 (dy0,dz0), j=1 (dy0,dz1) ----
            {
                const unsigned e0 = (gx ^ hy0 ^ hz0) & TMASK;
                const unsigned e1 = (gx ^ hy0 ^ hz1) & TMASK;
                const uint4 q0 = __ldg(tg + (e0 >> 2));
                const uint4 q1 = __ldg(tg + (e1 >> 2));
                const unsigned f0 = e0 ^ m, f1 = e1 ^ m;
                const unsigned xb0 = extra ? __ldg(tb + f0) : 0u;   // @P LDG
                const unsigned xb1 = extra ? __ldg(tb + f1) : 0u;
                const unsigned a0 = ext4(q0, e0 & 3u);
                const unsigned a1 = ext4(q1, e1 & 3u);
                const unsigned b0 = extra ? xb0 : ext4(q0, f0 & 3u);
                const unsigned b1 = extra ? xb1 : ext4(q1, f1 & 3u);
                const float2 va0 = h2f(a0), va1 = h2f(a1);
                const float2 vb0 = h2f(b0), vb1 = h2f(b1);
                r0  = w0*va0.x + w1*va1.x + w4*vb0.x + w5*vb1.x;
                r1  = w0*va0.y + w1*va1.y + w4*vb0.y + w5*vb1.y;
            }
            // ---- batch B: corner-pairs j=2 (dy1,dz0), j=3 (dy1,dz1) ----
            {
                const unsigned e2 = (gx ^ hy1 ^ hz0) & TMASK;
                const unsigned e3 = (gx ^ hy1 ^ hz1) & TMASK;
                const uint4 q2 = __ldg(tg + (e2 >> 2));
                const uint4 q3 = __ldg(tg + (e3 >> 2));
                const unsigned f2 = e2 ^ m, f3 = e3 ^ m;
                const unsigned xb2 = extra ? __ldg(tb + f2) : 0u;
                const unsigned xb3 = extra ? __ldg(tb + f3) : 0u;
                const unsigned a2 = ext4(q2, e2 & 3u);
                const unsigned a3 = ext4(q3, e3 & 3u);
                const unsigned b2 = extra ? xb2 : ext4(q2, f2 & 3u);
                const unsigned b3 = extra ? xb3 : ext4(q3, f3 & 3u);
                const float2 va2 = h2f(a2), va3 = h2f(a3);
                const float2 vb2 = h2f(b2), vb3 = h2f(b3);
                r0 += w2*va2.x + w3*va3.x + w6*vb2.x + w7*vb3.x;
                r1 += w2*va2.y + w3*va3.y + w6*vb2.y + w7*vb3.y;
            }

            s_out[pt][2*level + 0] = r0;
            s_out[pt][2*level + 1] = r1;
        }
    }

    // ---------------- dense levels: 640 pair-tasks over all lanes ----------
    // task d: lvl = d>>7 (128 tasks/level), pt = (d>>1)&63, k = d&1 (=dx).
    // Pairs (2 consecutive d) stay within one warp: 352 % 2 == 0.
    #pragma unroll
    for (int pass = 0; pass < 2; ++pass) {
        const int d = tid + pass * 352;
        if (d < 640) {
            const int lvl = d >> 7;
            const int pt  = (d >> 1) & 63;
            const int k   = d & 1;           // dx

            const float    sc   = c_scale[lvl];
            const unsigned res  = c_res[lvl];
            const unsigned res2 = c_res2[lvl];
            const unsigned coff = c_coff[lvl];

            const float x = s_c[pt*3+0], y = s_c[pt*3+1], z = s_c[pt*3+2];
            const float px = x*sc + 0.5f, py = y*sc + 0.5f, pz = z*sc + 0.5f;
            const float fx = floorf(px), fy = floorf(py), fz = floorf(pz);
            const float wx = px - fx,    wy = py - fy,    wz = pz - fz;
            const unsigned gx = (unsigned)fx, gy = (unsigned)fy, gz = (unsigned)fz;

            const unsigned cell = coff + gx + gy*res + gz*res2;
            const uint4 q = __ldg(&g_cells[(size_t)cell * 2 + k]);  // 4 corners

            const float iy = 1.0f - wy;
            const float izf = (1.0f - wz) * FINV, wzf = wz * FINV;
            const float w00 = iy*izf, w01 = iy*wzf, w10 = wy*izf, w11 = wy*wzf;
            const float2 c00 = h2f(q.x), c01 = h2f(q.y);
            const float2 c10 = h2f(q.z), c11 = h2f(q.w);
            const float wdx = k ? wx : 1.0f - wx;
            float f0 = wdx * (w00*c00.x + w01*c01.x + w10*c10.x + w11*c11.x);
            float f1 = wdx * (w00*c00.y + w01*c01.y + w10*c10.y + w11*c11.y);

            f0 += __shfl_xor_sync(0xffffffffu, f0, 1);
            f1 += __shfl_xor_sync(0xffffffffu, f1, 1);

            if (k == 0) {
                s_out[pt][2*lvl + 0] = f0;
                s_out[pt][2*lvl + 1] = f1;
            }
        }
    }
    __syncthreads();

    // Coalesced writeback: 1024 float2 = 8KB contiguous per block.
    #pragma unroll
    for (int idx = tid; idx < PTS * 16; idx += 352) {
        const int pp = idx >> 4;
        const int c  = (idx & 15) * 2;
        const int gp = pbase + pp;
        if (gp < n_points) {
            const float a = s_out[pp][c];
            const float b = s_out[pp][c + 1];
            float2* o = reinterpret_cast<float2*>(out + (size_t)gp * 32 + c);
            *o = make_float2(a, b);
        }
    }
}

extern "C" void kernel_launch(void* const* d_in, const int* in_sizes, int n_in,
                              void* d_out, int out_size) {
    const float*  coords = (const float*)d_in[0];   // [N, 3] f32
    const float2* table  = (const float2*)d_in[1];  // [16, 2^19, 2] f32
    float*        out    = (float*)d_out;           // [N, 32] f32
    const int n_points = in_sizes[0] / 3;

    hg_prep<<<PREP_BLOCKS, 256>>>(table);
    const int blocks = (n_points + PTS - 1) / PTS;
    hg_encode<<<blocks, 352>>>(coords, out, n_points);
}